// round 1
// baseline (speedup 1.0000x reference)
#include <cuda_runtime.h>
#include <cstdint>

// Shapes (fixed per reference): B=16, C=512, H=W=64, S=512
#define B_  16
#define C_  512
#define HW_ 4096
#define S_  512

// Scratch (no allocation allowed — device globals)
__device__ __align__(16) float g_invrms[B_ * HW_];   // 262 KB
__device__ __align__(16) float g_style[B_ * 2 * C_]; // 64 KB

// ---------------------------------------------------------------------------
// Pass S: s[b, :] = style[b, :] @ lin_W + lin_b   (16 x 512 @ 512 x 1024)
// One block per b; thread t computes columns t, t+256, t+512, t+768.
// ---------------------------------------------------------------------------
__global__ __launch_bounds__(256) void pass_s(
    const float* __restrict__ style,
    const float* __restrict__ W,
    const float* __restrict__ bias)
{
    __shared__ float ss[S_];
    const int b = blockIdx.x;
    for (int i = threadIdx.x; i < S_; i += 256) ss[i] = style[b * S_ + i];
    __syncthreads();

    const int c0 = threadIdx.x;
    float a0 = 0.f, a1 = 0.f, a2 = 0.f, a3 = 0.f;
#pragma unroll 4
    for (int k = 0; k < S_; k++) {
        const float sv = ss[k];
        const float* row = W + (size_t)k * 1024;
        a0 = fmaf(sv, row[c0      ], a0);
        a1 = fmaf(sv, row[c0 + 256], a1);
        a2 = fmaf(sv, row[c0 + 512], a2);
        a3 = fmaf(sv, row[c0 + 768], a3);
    }
    float* out = g_style + b * 1024;
    out[c0      ] = a0 + bias[c0      ];
    out[c0 + 256] = a1 + bias[c0 + 256];
    out[c0 + 512] = a2 + bias[c0 + 512];
    out[c0 + 768] = a3 + bias[c0 + 768];
}

// ---------------------------------------------------------------------------
// Pass A: per-pixel inverse RMS over channels of x' = leaky(x + nw[c]*noise)
// Grid: B_*HW_/256 = 256 blocks, 256 threads; thread owns one pixel, loops C.
// ---------------------------------------------------------------------------
__global__ __launch_bounds__(256) void pass_a(
    const float* __restrict__ x,
    const float* __restrict__ noise,
    const float* __restrict__ nw)
{
    __shared__ float snw[C_];
    for (int i = threadIdx.x; i < C_; i += 256) snw[i] = nw[i];
    __syncthreads();

    const int b   = blockIdx.x >> 4;           // 16 pixel-tiles per batch
    const int pix = ((blockIdx.x & 15) << 8) + threadIdx.x;
    const float nz = noise[b * HW_ + pix];
    const float* xp = x + (size_t)b * C_ * HW_ + pix;

    float acc = 0.f;
#pragma unroll 8
    for (int c = 0; c < C_; c++) {
        float v = __ldg(xp + (size_t)c * HW_) + snw[c] * nz;
        v = (v >= 0.f) ? v : 0.2f * v;
        acc = fmaf(v, v, acc);
    }
    g_invrms[b * HW_ + pix] = rsqrtf(acc * (1.f / (float)C_) + 1e-8f);
}

// ---------------------------------------------------------------------------
// Pass BC: one block per (b,c) plane (8192 blocks, 256 threads).
//   y = leaky(x + nw[c]*noise) * invrms        (16 values/thread, registers)
//   mean/var over HW via block reduction, then
//   out = y * (istd*scale) + (shift - mean*istd*scale)
// ---------------------------------------------------------------------------
__global__ __launch_bounds__(256) void pass_bc(
    const float* __restrict__ x,
    const float* __restrict__ noise,
    const float* __restrict__ nw,
    float* __restrict__ out)
{
    const int b = blockIdx.x >> 9;     // C_=512 planes per batch
    const int c = blockIdx.x & (C_ - 1);
    const size_t plane = ((size_t)b * C_ + c) * HW_;

    const float4* xp = (const float4*)(x + plane);
    const float4* np = (const float4*)(noise + (size_t)b * HW_);
    const float4* ip = (const float4*)(g_invrms + b * HW_);
    const float w = nw[c];

    float4 y[4];
    float sum = 0.f, sumsq = 0.f;

#pragma unroll
    for (int j = 0; j < 4; j++) {
        const int i = threadIdx.x + j * 256;
        float4 xv = xp[i];
        float4 nv = np[i];
        float4 iv = ip[i];
        float4 yv;
        {
            float v;
            v = fmaf(w, nv.x, xv.x); v = (v >= 0.f) ? v : 0.2f * v; yv.x = v * iv.x;
            v = fmaf(w, nv.y, xv.y); v = (v >= 0.f) ? v : 0.2f * v; yv.y = v * iv.y;
            v = fmaf(w, nv.z, xv.z); v = (v >= 0.f) ? v : 0.2f * v; yv.z = v * iv.z;
            v = fmaf(w, nv.w, xv.w); v = (v >= 0.f) ? v : 0.2f * v; yv.w = v * iv.w;
        }
        y[j] = yv;
        sum   += yv.x + yv.y + yv.z + yv.w;
        sumsq += yv.x * yv.x + yv.y * yv.y + yv.z * yv.z + yv.w * yv.w;
    }

    // Block reduction of (sum, sumsq)
    const int lane = threadIdx.x & 31;
    const int warp = threadIdx.x >> 5;
#pragma unroll
    for (int off = 16; off > 0; off >>= 1) {
        sum   += __shfl_xor_sync(0xFFFFFFFFu, sum,   off);
        sumsq += __shfl_xor_sync(0xFFFFFFFFu, sumsq, off);
    }
    __shared__ float s_sum[8], s_sq[8], s_stats[2];
    if (lane == 0) { s_sum[warp] = sum; s_sq[warp] = sumsq; }
    __syncthreads();
    if (threadIdx.x == 0) {
        float ts = 0.f, tq = 0.f;
#pragma unroll
        for (int k = 0; k < 8; k++) { ts += s_sum[k]; tq += s_sq[k]; }
        const float mean = ts * (1.f / (float)HW_);
        const float var  = tq * (1.f / (float)HW_) - mean * mean;
        s_stats[0] = mean;
        s_stats[1] = rsqrtf(var + 1e-5f);
    }
    __syncthreads();
    const float mean = s_stats[0];
    const float istd = s_stats[1];

    const float scale = g_style[b * 1024 + c] + 1.f;           // s[:,0] + 1
    const float shift = g_style[b * 1024 + C_ + c];            // s[:,1]
    const float a = istd * scale;
    const float d = shift - mean * a;

    float4* op = (float4*)(out + plane);
#pragma unroll
    for (int j = 0; j < 4; j++) {
        const int i = threadIdx.x + j * 256;
        float4 yv = y[j];
        float4 ov;
        ov.x = fmaf(yv.x, a, d);
        ov.y = fmaf(yv.y, a, d);
        ov.z = fmaf(yv.z, a, d);
        ov.w = fmaf(yv.w, a, d);
        op[i] = ov;
    }
}

// ---------------------------------------------------------------------------
// Inputs (metadata order): x, noise, style, noise_weight, lin_W, lin_b
// Output: float32 [B, C, H, W]
// ---------------------------------------------------------------------------
extern "C" void kernel_launch(void* const* d_in, const int* in_sizes, int n_in,
                              void* d_out, int out_size)
{
    const float* x     = (const float*)d_in[0];
    const float* noise = (const float*)d_in[1];
    const float* style = (const float*)d_in[2];
    const float* nw    = (const float*)d_in[3];
    const float* lin_W = (const float*)d_in[4];
    const float* lin_b = (const float*)d_in[5];
    float* out = (float*)d_out;

    pass_s<<<B_, 256>>>(style, lin_W, lin_b);
    pass_a<<<(B_ * HW_) / 256, 256>>>(x, noise, nw);
    pass_bc<<<B_ * C_, 256>>>(x, noise, nw, out);
}

// round 2
// speedup vs baseline: 1.3637x; 1.3637x over previous
#include <cuda_runtime.h>
#include <cstdint>

// Shapes (fixed per reference): B=16, C=512, H=W=64, S=512
#define B_  16
#define C_  512
#define HW_ 4096
#define S_  512

// Scratch (no allocation allowed — device globals)
__device__ __align__(16) float g_invrms[B_ * HW_];   // 262 KB
__device__ __align__(16) float g_style[B_ * 2 * C_]; // 64 KB

// ---------------------------------------------------------------------------
// Fused pass S+A (independent work, one launch):
//   blocks [0, 64):    style GEMM  s[b,:] = style[b,:] @ W + bias
//                      (b = bx>>2, 256-column chunk = bx&3, 1 col/thread)
//   blocks [64, 192):  per-pixel inv-RMS over channels of
//                      x' = leaky(x + nw[c]*noise); 2 pixels/thread (float2)
// ---------------------------------------------------------------------------
#define SA_GEMM_BLOCKS 64
#define SA_A_BLOCKS    128   // 16 b x 8 tiles of 512 pixels

__global__ __launch_bounds__(256) void pass_sa(
    const float* __restrict__ x,
    const float* __restrict__ noise,
    const float* __restrict__ nw,
    const float* __restrict__ style,
    const float* __restrict__ W,
    const float* __restrict__ bias)
{
    __shared__ float sh[S_];

    if (blockIdx.x < SA_GEMM_BLOCKS) {
        // ----- GEMM part -----
        const int b     = blockIdx.x >> 2;
        const int chunk = blockIdx.x & 3;
        for (int i = threadIdx.x; i < S_; i += 256) sh[i] = style[b * S_ + i];
        __syncthreads();

        const int col = chunk * 256 + threadIdx.x;   // 0..1023
        float acc = 0.f;
#pragma unroll 16
        for (int k = 0; k < S_; k++) {
            acc = fmaf(sh[k], __ldg(W + (size_t)k * 1024 + col), acc);
        }
        g_style[b * 1024 + col] = acc + __ldg(bias + col);
    } else {
        // ----- inv-RMS part -----
        const int bx  = blockIdx.x - SA_GEMM_BLOCKS;  // 0..127
        for (int i = threadIdx.x; i < C_; i += 256) sh[i] = nw[i];
        __syncthreads();

        const int b    = bx >> 3;                     // 8 tiles per batch
        const int pix0 = ((bx & 7) << 9) + threadIdx.x * 2;  // tile of 512 px

        const float2 nz = *(const float2*)(noise + b * HW_ + pix0);
        const float* xp = x + (size_t)b * C_ * HW_ + pix0;

        float a0 = 0.f, a1 = 0.f;
#pragma unroll 8
        for (int c = 0; c < C_; c++) {
            const float2 xv = *(const float2*)(xp + (size_t)c * HW_);
            const float wch = sh[c];
            float v0 = fmaf(wch, nz.x, xv.x);
            float v1 = fmaf(wch, nz.y, xv.y);
            v0 = (v0 >= 0.f) ? v0 : 0.2f * v0;
            v1 = (v1 >= 0.f) ? v1 : 0.2f * v1;
            a0 = fmaf(v0, v0, a0);
            a1 = fmaf(v1, v1, a1);
        }
        float* op = g_invrms + b * HW_ + pix0;
        op[0] = rsqrtf(a0 * (1.f / (float)C_) + 1e-8f);
        op[1] = rsqrtf(a1 * (1.f / (float)C_) + 1e-8f);
    }
}

// ---------------------------------------------------------------------------
// Pass BC: one block per (b,c) plane (8192 blocks, 256 threads).
//   y = leaky(x + nw[c]*noise) * invrms        (16 values/thread, registers)
//   mean/var over HW via block reduction, then
//   out = y * (istd*scale) + (shift - mean*istd*scale)
// ---------------------------------------------------------------------------
__global__ __launch_bounds__(256) void pass_bc(
    const float* __restrict__ x,
    const float* __restrict__ noise,
    const float* __restrict__ nw,
    float* __restrict__ out)
{
    const int b = blockIdx.x >> 9;     // C_=512 planes per batch
    const int c = blockIdx.x & (C_ - 1);
    const size_t plane = ((size_t)b * C_ + c) * HW_;

    const float4* xp = (const float4*)(x + plane);
    const float4* np = (const float4*)(noise + (size_t)b * HW_);
    const float4* ip = (const float4*)(g_invrms + b * HW_);
    const float w = nw[c];

    float4 y[4];
    float sum = 0.f, sumsq = 0.f;

#pragma unroll
    for (int j = 0; j < 4; j++) {
        const int i = threadIdx.x + j * 256;
        float4 xv = xp[i];
        float4 nv = np[i];
        float4 iv = ip[i];
        float4 yv;
        {
            float v;
            v = fmaf(w, nv.x, xv.x); v = (v >= 0.f) ? v : 0.2f * v; yv.x = v * iv.x;
            v = fmaf(w, nv.y, xv.y); v = (v >= 0.f) ? v : 0.2f * v; yv.y = v * iv.y;
            v = fmaf(w, nv.z, xv.z); v = (v >= 0.f) ? v : 0.2f * v; yv.z = v * iv.z;
            v = fmaf(w, nv.w, xv.w); v = (v >= 0.f) ? v : 0.2f * v; yv.w = v * iv.w;
        }
        y[j] = yv;
        sum   += yv.x + yv.y + yv.z + yv.w;
        sumsq += yv.x * yv.x + yv.y * yv.y + yv.z * yv.z + yv.w * yv.w;
    }

    // Block reduction of (sum, sumsq)
    const int lane = threadIdx.x & 31;
    const int warp = threadIdx.x >> 5;
#pragma unroll
    for (int off = 16; off > 0; off >>= 1) {
        sum   += __shfl_xor_sync(0xFFFFFFFFu, sum,   off);
        sumsq += __shfl_xor_sync(0xFFFFFFFFu, sumsq, off);
    }
    __shared__ float s_sum[8], s_sq[8], s_stats[2];
    if (lane == 0) { s_sum[warp] = sum; s_sq[warp] = sumsq; }
    __syncthreads();
    if (threadIdx.x == 0) {
        float ts = 0.f, tq = 0.f;
#pragma unroll
        for (int k = 0; k < 8; k++) { ts += s_sum[k]; tq += s_sq[k]; }
        const float mean = ts * (1.f / (float)HW_);
        const float var  = tq * (1.f / (float)HW_) - mean * mean;
        s_stats[0] = mean;
        s_stats[1] = rsqrtf(var + 1e-5f);
    }
    __syncthreads();
    const float mean = s_stats[0];
    const float istd = s_stats[1];

    const float scale = g_style[b * 1024 + c] + 1.f;           // s[:,0] + 1
    const float shift = g_style[b * 1024 + C_ + c];            // s[:,1]
    const float a = istd * scale;
    const float d = shift - mean * a;

    float4* op = (float4*)(out + plane);
#pragma unroll
    for (int j = 0; j < 4; j++) {
        const int i = threadIdx.x + j * 256;
        float4 yv = y[j];
        float4 ov;
        ov.x = fmaf(yv.x, a, d);
        ov.y = fmaf(yv.y, a, d);
        ov.z = fmaf(yv.z, a, d);
        ov.w = fmaf(yv.w, a, d);
        op[i] = ov;
    }
}

// ---------------------------------------------------------------------------
// Inputs (metadata order): x, noise, style, noise_weight, lin_W, lin_b
// Output: float32 [B, C, H, W]
// ---------------------------------------------------------------------------
extern "C" void kernel_launch(void* const* d_in, const int* in_sizes, int n_in,
                              void* d_out, int out_size)
{
    const float* x     = (const float*)d_in[0];
    const float* noise = (const float*)d_in[1];
    const float* style = (const float*)d_in[2];
    const float* nw    = (const float*)d_in[3];
    const float* lin_W = (const float*)d_in[4];
    const float* lin_b = (const float*)d_in[5];
    float* out = (float*)d_out;

    pass_sa<<<SA_GEMM_BLOCKS + SA_A_BLOCKS, 256>>>(x, noise, nw, style, lin_W, lin_b);
    pass_bc<<<B_ * C_, 256>>>(x, noise, nw, out);
}

// round 3
// speedup vs baseline: 2.1889x; 1.6051x over previous
#include <cuda_runtime.h>
#include <cstdint>

// Shapes (fixed per reference): B=16, C=512, H=W=64, S=512
#define B_   16
#define C_   512
#define HW_  4096
#define S_   512
#define NCC  8          // C-chunks in pass K1
#define CCW  (C_/NCC)   // 64 channels per chunk

// Scratch (no allocation allowed — device globals)
__device__ __align__(16) float g_part[NCC * B_ * HW_];  // 2 MB partial sumsq
__device__ __align__(16) float g_invrms[B_ * HW_];      // 262 KB
__device__ __align__(16) float g_style[B_ * 2 * C_];    // 64 KB

// ---------------------------------------------------------------------------
// K1: partial sum-of-squares of x' = leaky(x + nw[c]*noise) over a 64-channel
// chunk, for a 1024-pixel tile. Grid (NCC, 4, B_), 256 threads, 4 px/thread.
// ---------------------------------------------------------------------------
__global__ __launch_bounds__(256) void k1_partial(
    const float* __restrict__ x,
    const float* __restrict__ noise,
    const float* __restrict__ nw)
{
    __shared__ float snw[CCW];
    const int cc = blockIdx.x, tile = blockIdx.y, b = blockIdx.z;
    if (threadIdx.x < CCW) snw[threadIdx.x] = nw[cc * CCW + threadIdx.x];
    __syncthreads();

    const int px = tile * 1024 + threadIdx.x * 4;
    const float4 nz = *(const float4*)(noise + b * HW_ + px);
    const float* xp = x + ((size_t)b * C_ + cc * CCW) * HW_ + px;

    float4 acc = make_float4(0.f, 0.f, 0.f, 0.f);
#pragma unroll 8
    for (int c = 0; c < CCW; c++) {
        const float4 xv = *(const float4*)(xp + (size_t)c * HW_);
        const float w = snw[c];
        float v;
        v = fmaf(w, nz.x, xv.x); v = (v >= 0.f) ? v : 0.2f * v; acc.x = fmaf(v, v, acc.x);
        v = fmaf(w, nz.y, xv.y); v = (v >= 0.f) ? v : 0.2f * v; acc.y = fmaf(v, v, acc.y);
        v = fmaf(w, nz.z, xv.z); v = (v >= 0.f) ? v : 0.2f * v; acc.z = fmaf(v, v, acc.z);
        v = fmaf(w, nz.w, xv.w); v = (v >= 0.f) ? v : 0.2f * v; acc.w = fmaf(v, v, acc.w);
    }
    *(float4*)(g_part + ((size_t)cc * B_ + b) * HW_ + px) = acc;
}

// ---------------------------------------------------------------------------
// K2: blocks [0,64)  : combine 8 partials -> invrms (1024 px/block, float4)
//     blocks [64,192): style GEMM, 128 cols/block, K split in 2 per thread
// ---------------------------------------------------------------------------
__global__ __launch_bounds__(256) void k2_combine_gemm(
    const float* __restrict__ style,
    const float* __restrict__ W,
    const float* __restrict__ bias)
{
    __shared__ float ss[S_];
    __shared__ float sp[256];
    const int tid = threadIdx.x;

    if (blockIdx.x < 64) {
        const int b = blockIdx.x >> 2, tile = blockIdx.x & 3;
        const int px = tile * 1024 + tid * 4;
        float4 s = make_float4(0.f, 0.f, 0.f, 0.f);
#pragma unroll
        for (int cc = 0; cc < NCC; cc++) {
            const float4 p = *(const float4*)(g_part + ((size_t)cc * B_ + b) * HW_ + px);
            s.x += p.x; s.y += p.y; s.z += p.z; s.w += p.w;
        }
        float4 r;
        r.x = rsqrtf(s.x * (1.f / (float)C_) + 1e-8f);
        r.y = rsqrtf(s.y * (1.f / (float)C_) + 1e-8f);
        r.z = rsqrtf(s.z * (1.f / (float)C_) + 1e-8f);
        r.w = rsqrtf(s.w * (1.f / (float)C_) + 1e-8f);
        *(float4*)(g_invrms + b * HW_ + px) = r;
    } else {
        const int gb = blockIdx.x - 64;
        const int b = gb >> 3, chunk = gb & 7;
        for (int i = tid; i < S_; i += 256) ss[i] = style[b * S_ + i];
        __syncthreads();

        const int col = chunk * 128 + (tid & 127);
        const int k0  = (tid >> 7) * 256;
        float acc = 0.f;
#pragma unroll 8
        for (int k = k0; k < k0 + 256; k++)
            acc = fmaf(ss[k], __ldg(W + (size_t)k * 1024 + col), acc);
        sp[tid] = acc;
        __syncthreads();
        if (tid < 128)
            g_style[b * 1024 + col] = sp[tid] + sp[tid + 128] + __ldg(bias + col);
    }
}

// ---------------------------------------------------------------------------
// K3: 4 planes (same b) per block; noise + invrms staged in shared once.
//   y = leaky(x + nw[c]*noise) * invrms  (held in regs), block-reduce
//   mean/var, out = y*(istd*scale) + (shift - mean*istd*scale)
// Grid: B_ * 128 blocks, 256 threads.
// ---------------------------------------------------------------------------
__global__ __launch_bounds__(256) void k3_bc(
    const float* __restrict__ x,
    const float* __restrict__ noise,
    const float* __restrict__ nw,
    float* __restrict__ out)
{
    __shared__ float s_nz[HW_];
    __shared__ float s_ir[HW_];
    __shared__ float s_sum[8], s_sq[8], s_stats[2];

    const int b   = blockIdx.x >> 7;
    const int grp = blockIdx.x & 127;
    const int tid = threadIdx.x;
    const int lane = tid & 31, warp = tid >> 5;

    {
        const float4* np = (const float4*)(noise + (size_t)b * HW_);
        const float4* ip = (const float4*)(g_invrms + b * HW_);
#pragma unroll
        for (int i = 0; i < HW_ / 4 / 256; i++) {
            ((float4*)s_nz)[tid + i * 256] = np[tid + i * 256];
            ((float4*)s_ir)[tid + i * 256] = ip[tid + i * 256];
        }
    }
    __syncthreads();

#pragma unroll 1
    for (int pc = 0; pc < 4; pc++) {
        const int c = grp * 4 + pc;
        const size_t plane = ((size_t)b * C_ + c) * HW_;
        const float w = __ldg(nw + c);
        const float4* xp = (const float4*)(x + plane);

        float4 y[4];
        float sum = 0.f, sumsq = 0.f;
#pragma unroll
        for (int j = 0; j < 4; j++) {
            const int i = tid + j * 256;
            const float4 xv = xp[i];
            const float4 nv = ((const float4*)s_nz)[i];
            const float4 iv = ((const float4*)s_ir)[i];
            float4 yv;
            float v;
            v = fmaf(w, nv.x, xv.x); v = (v >= 0.f) ? v : 0.2f * v; yv.x = v * iv.x;
            v = fmaf(w, nv.y, xv.y); v = (v >= 0.f) ? v : 0.2f * v; yv.y = v * iv.y;
            v = fmaf(w, nv.z, xv.z); v = (v >= 0.f) ? v : 0.2f * v; yv.z = v * iv.z;
            v = fmaf(w, nv.w, xv.w); v = (v >= 0.f) ? v : 0.2f * v; yv.w = v * iv.w;
            y[j] = yv;
            sum   += yv.x + yv.y + yv.z + yv.w;
            sumsq += yv.x * yv.x + yv.y * yv.y + yv.z * yv.z + yv.w * yv.w;
        }

#pragma unroll
        for (int off = 16; off > 0; off >>= 1) {
            sum   += __shfl_xor_sync(0xFFFFFFFFu, sum,   off);
            sumsq += __shfl_xor_sync(0xFFFFFFFFu, sumsq, off);
        }
        if (lane == 0) { s_sum[warp] = sum; s_sq[warp] = sumsq; }
        __syncthreads();
        if (tid == 0) {
            float ts = 0.f, tq = 0.f;
#pragma unroll
            for (int k = 0; k < 8; k++) { ts += s_sum[k]; tq += s_sq[k]; }
            const float mean = ts * (1.f / (float)HW_);
            const float var  = tq * (1.f / (float)HW_) - mean * mean;
            s_stats[0] = mean;
            s_stats[1] = rsqrtf(var + 1e-5f);
        }
        __syncthreads();
        const float mean = s_stats[0];
        const float istd = s_stats[1];

        const float scale = g_style[b * 1024 + c] + 1.f;   // s[:,0] + 1
        const float shift = g_style[b * 1024 + C_ + c];    // s[:,1]
        const float a = istd * scale;
        const float d = shift - mean * a;

        float4* op = (float4*)(out + plane);
#pragma unroll
        for (int j = 0; j < 4; j++) {
            const int i = tid + j * 256;
            const float4 yv = y[j];
            float4 ov;
            ov.x = fmaf(yv.x, a, d);
            ov.y = fmaf(yv.y, a, d);
            ov.z = fmaf(yv.z, a, d);
            ov.w = fmaf(yv.w, a, d);
            op[i] = ov;
        }
    }
}

// ---------------------------------------------------------------------------
// Inputs (metadata order): x, noise, style, noise_weight, lin_W, lin_b
// Output: float32 [B, C, H, W]
// ---------------------------------------------------------------------------
extern "C" void kernel_launch(void* const* d_in, const int* in_sizes, int n_in,
                              void* d_out, int out_size)
{
    const float* x     = (const float*)d_in[0];
    const float* noise = (const float*)d_in[1];
    const float* style = (const float*)d_in[2];
    const float* nw    = (const float*)d_in[3];
    const float* lin_W = (const float*)d_in[4];
    const float* lin_b = (const float*)d_in[5];
    float* out = (float*)d_out;

    dim3 g1(NCC, 4, B_);
    k1_partial<<<g1, 256>>>(x, noise, nw);
    k2_combine_gemm<<<192, 256>>>(style, lin_W, lin_b);
    k3_bc<<<B_ * 128, 256>>>(x, noise, nw, out);
}

// round 4
// speedup vs baseline: 2.3551x; 1.0760x over previous
#include <cuda_runtime.h>
#include <cstdint>

// Shapes (fixed per reference): B=16, C=512, H=W=64, S=512
#define B_   16
#define C_   512
#define HW_  4096
#define S_   512
#define NCC  8          // C-chunks in pass K1
#define CCW  (C_/NCC)   // 64 channels per chunk

// Scratch (no allocation allowed — device globals)
__device__ __align__(16) float g_part[NCC * B_ * HW_];  // 2 MB partial sumsq
__device__ __align__(16) float g_invrms[B_ * HW_];      // 262 KB
__device__ __align__(16) float g_style[B_ * 2 * C_];    // 64 KB

// ---------------------------------------------------------------------------
// K1: partial sum-of-squares of x' = leaky(x + nw[c]*noise) over a 64-channel
// chunk, for a 512-pixel tile. Grid (NCC, 8, B_) = 1024 blocks, 256 threads,
// 2 px/thread (float2).
// ---------------------------------------------------------------------------
__global__ __launch_bounds__(256) void k1_partial(
    const float* __restrict__ x,
    const float* __restrict__ noise,
    const float* __restrict__ nw)
{
    __shared__ float snw[CCW];
    const int cc = blockIdx.x, tile = blockIdx.y, b = blockIdx.z;
    if (threadIdx.x < CCW) snw[threadIdx.x] = nw[cc * CCW + threadIdx.x];
    __syncthreads();

    const int px = tile * 512 + threadIdx.x * 2;
    const float2 nz = *(const float2*)(noise + b * HW_ + px);
    const float* xp = x + ((size_t)b * C_ + cc * CCW) * HW_ + px;

    float a0 = 0.f, a1 = 0.f;
#pragma unroll 8
    for (int c = 0; c < CCW; c++) {
        const float2 xv = *(const float2*)(xp + (size_t)c * HW_);
        const float w = snw[c];
        float v0 = fmaf(w, nz.x, xv.x);
        float v1 = fmaf(w, nz.y, xv.y);
        v0 = (v0 >= 0.f) ? v0 : 0.2f * v0;
        v1 = (v1 >= 0.f) ? v1 : 0.2f * v1;
        a0 = fmaf(v0, v0, a0);
        a1 = fmaf(v1, v1, a1);
    }
    float2 r; r.x = a0; r.y = a1;
    *(float2*)(g_part + ((size_t)cc * B_ + b) * HW_ + px) = r;
}

// ---------------------------------------------------------------------------
// K2: blocks [0,64)   : combine 8 partials -> invrms (1024 px/block, float4)
//     blocks [64,320) : style GEMM; block = (b, 64-col chunk); thread =
//                       (col 0..63) x (K-slice 0..3 of 128); smem tree-combine
// ---------------------------------------------------------------------------
__global__ __launch_bounds__(256) void k2_combine_gemm(
    const float* __restrict__ style,
    const float* __restrict__ W,
    const float* __restrict__ bias)
{
    __shared__ float ss[S_];
    __shared__ float sp[256];
    const int tid = threadIdx.x;

    if (blockIdx.x < 64) {
        const int b = blockIdx.x >> 2, tile = blockIdx.x & 3;
        const int px = tile * 1024 + tid * 4;
        float4 s = make_float4(0.f, 0.f, 0.f, 0.f);
#pragma unroll
        for (int cc = 0; cc < NCC; cc++) {
            const float4 p = *(const float4*)(g_part + ((size_t)cc * B_ + b) * HW_ + px);
            s.x += p.x; s.y += p.y; s.z += p.z; s.w += p.w;
        }
        float4 r;
        r.x = rsqrtf(s.x * (1.f / (float)C_) + 1e-8f);
        r.y = rsqrtf(s.y * (1.f / (float)C_) + 1e-8f);
        r.z = rsqrtf(s.z * (1.f / (float)C_) + 1e-8f);
        r.w = rsqrtf(s.w * (1.f / (float)C_) + 1e-8f);
        *(float4*)(g_invrms + b * HW_ + px) = r;
    } else {
        const int gb = blockIdx.x - 64;          // 0..255
        const int b = gb >> 4, chunk = gb & 15;  // 16 chunks of 64 cols
        for (int i = tid; i < S_; i += 256) ss[i] = style[b * S_ + i];
        __syncthreads();

        const int col = chunk * 64 + (tid & 63);
        const int k0  = (tid >> 6) * 128;        // 4 K-slices of 128
        float acc = 0.f;
#pragma unroll 8
        for (int k = k0; k < k0 + 128; k++)
            acc = fmaf(ss[k], __ldg(W + (size_t)k * 1024 + col), acc);
        sp[tid] = acc;
        __syncthreads();
        if (tid < 64)
            g_style[b * 1024 + col] = sp[tid] + sp[tid + 64] + sp[tid + 128]
                                    + sp[tid + 192] + __ldg(bias + col);
    }
}

// ---------------------------------------------------------------------------
// K3: one (b,c) plane per block; 512 threads x 8 px (2 float4 each).
//   y = leaky(x + nw[c]*noise) * invrms  (held in regs), block-reduce
//   mean/var, out = y*(istd*scale) + (shift - mean*istd*scale)
// noise / invrms reads hit L2 (262 KB each, reused 512x).
// ---------------------------------------------------------------------------
__global__ __launch_bounds__(512) void k3_bc(
    const float* __restrict__ x,
    const float* __restrict__ noise,
    const float* __restrict__ nw,
    float* __restrict__ out)
{
    const int b = blockIdx.x >> 9;
    const int c = blockIdx.x & (C_ - 1);
    const size_t plane = ((size_t)b * C_ + c) * HW_;

    const float4* xp = (const float4*)(x + plane);
    const float4* np = (const float4*)(noise + (size_t)b * HW_);
    const float4* ip = (const float4*)(g_invrms + b * HW_);
    const float w = __ldg(nw + c);

    const int tid = threadIdx.x;
    float4 y[2];
    float sum = 0.f, sumsq = 0.f;

#pragma unroll
    for (int j = 0; j < 2; j++) {
        const int i = tid + j * 512;            // 1024 float4 per plane
        const float4 xv = xp[i];
        const float4 nv = np[i];
        const float4 iv = ip[i];
        float4 yv;
        float v;
        v = fmaf(w, nv.x, xv.x); v = (v >= 0.f) ? v : 0.2f * v; yv.x = v * iv.x;
        v = fmaf(w, nv.y, xv.y); v = (v >= 0.f) ? v : 0.2f * v; yv.y = v * iv.y;
        v = fmaf(w, nv.z, xv.z); v = (v >= 0.f) ? v : 0.2f * v; yv.z = v * iv.z;
        v = fmaf(w, nv.w, xv.w); v = (v >= 0.f) ? v : 0.2f * v; yv.w = v * iv.w;
        y[j] = yv;
        sum   += yv.x + yv.y + yv.z + yv.w;
        sumsq += yv.x * yv.x + yv.y * yv.y + yv.z * yv.z + yv.w * yv.w;
    }

    // Block reduction over 16 warps
    const int lane = tid & 31, warp = tid >> 5;
#pragma unroll
    for (int off = 16; off > 0; off >>= 1) {
        sum   += __shfl_xor_sync(0xFFFFFFFFu, sum,   off);
        sumsq += __shfl_xor_sync(0xFFFFFFFFu, sumsq, off);
    }
    __shared__ float s_sum[16], s_sq[16], s_stats[2];
    if (lane == 0) { s_sum[warp] = sum; s_sq[warp] = sumsq; }
    __syncthreads();
    if (warp == 0) {
        float ts = (lane < 16) ? s_sum[lane] : 0.f;
        float tq = (lane < 16) ? s_sq[lane]  : 0.f;
#pragma unroll
        for (int off = 8; off > 0; off >>= 1) {
            ts += __shfl_xor_sync(0xFFFFFFFFu, ts, off);
            tq += __shfl_xor_sync(0xFFFFFFFFu, tq, off);
        }
        if (lane == 0) {
            const float mean = ts * (1.f / (float)HW_);
            const float var  = tq * (1.f / (float)HW_) - mean * mean;
            s_stats[0] = mean;
            s_stats[1] = rsqrtf(var + 1e-5f);
        }
    }
    __syncthreads();
    const float mean = s_stats[0];
    const float istd = s_stats[1];

    const float scale = g_style[b * 1024 + c] + 1.f;   // s[:,0] + 1
    const float shift = g_style[b * 1024 + C_ + c];    // s[:,1]
    const float a = istd * scale;
    const float d = shift - mean * a;

    float4* op = (float4*)(out + plane);
#pragma unroll
    for (int j = 0; j < 2; j++) {
        const int i = tid + j * 512;
        const float4 yv = y[j];
        float4 ov;
        ov.x = fmaf(yv.x, a, d);
        ov.y = fmaf(yv.y, a, d);
        ov.z = fmaf(yv.z, a, d);
        ov.w = fmaf(yv.w, a, d);
        op[i] = ov;
    }
}

// ---------------------------------------------------------------------------
// Inputs (metadata order): x, noise, style, noise_weight, lin_W, lin_b
// Output: float32 [B, C, H, W]
// ---------------------------------------------------------------------------
extern "C" void kernel_launch(void* const* d_in, const int* in_sizes, int n_in,
                              void* d_out, int out_size)
{
    const float* x     = (const float*)d_in[0];
    const float* noise = (const float*)d_in[1];
    const float* style = (const float*)d_in[2];
    const float* nw    = (const float*)d_in[3];
    const float* lin_W = (const float*)d_in[4];
    const float* lin_b = (const float*)d_in[5];
    float* out = (float*)d_out;

    dim3 g1(NCC, 8, B_);
    k1_partial<<<g1, 256>>>(x, noise, nw);
    k2_combine_gemm<<<320, 256>>>(style, lin_W, lin_b);
    k3_bc<<<B_ * C_, 512>>>(x, noise, nw, out);
}

// round 5
// speedup vs baseline: 2.8617x; 1.2151x over previous
#include <cuda_runtime.h>
#include <cstdint>

// Shapes (fixed per reference): B=16, C=512, H=W=64, S=512
#define B_   16
#define C_   512
#define HW_  4096
#define S_   512
#define NCC  16         // C-chunks in pass K1
#define CCW  (C_/NCC)   // 32 channels per chunk

// Scratch (no allocation allowed — device globals)
__device__ __align__(16) float g_part[NCC * B_ * HW_];  // 4 MB partial sumsq
__device__ __align__(16) float g_invrms[B_ * HW_];      // 262 KB
__device__ __align__(16) float g_style[B_ * 2 * C_];    // 64 KB

// ---------------------------------------------------------------------------
// K1 (fused): blocks [0,1024): partial sum-of-squares of
//   x' = leaky(x + nw[c]*noise) over a 32-channel chunk, 1024-pixel tile.
//   bx -> cc = bx&15, tile = (bx>>4)&3, b = bx>>6. 256 thr x 4 px (float4).
//   blocks [1024,1280): style GEMM s[b,:] = style[b,:] @ W + bias
//   (overlaps under the streaming; independent of k1 data).
// ---------------------------------------------------------------------------
#define K1_BLOCKS   1024
#define GEMM_BLOCKS 256

__global__ __launch_bounds__(256) void k1_fused(
    const float* __restrict__ x,
    const float* __restrict__ noise,
    const float* __restrict__ nw,
    const float* __restrict__ style,
    const float* __restrict__ W,
    const float* __restrict__ bias)
{
    const int tid = threadIdx.x;

    if (blockIdx.x < K1_BLOCKS) {
        __shared__ float snw[CCW];
        const int cc   = blockIdx.x & 15;
        const int tile = (blockIdx.x >> 4) & 3;
        const int b    = blockIdx.x >> 6;
        if (tid < CCW) snw[tid] = nw[cc * CCW + tid];
        __syncthreads();

        const int px = tile * 1024 + tid * 4;
        const float4 nz = *(const float4*)(noise + b * HW_ + px);
        const float* xp = x + ((size_t)b * C_ + cc * CCW) * HW_ + px;

        float4 acc = make_float4(0.f, 0.f, 0.f, 0.f);
#pragma unroll
        for (int c = 0; c < CCW; c++) {
            const float4 xv = __ldcs((const float4*)(xp + (size_t)c * HW_));
            const float w = snw[c];
            float v;
            v = fmaf(w, nz.x, xv.x); v = (v >= 0.f) ? v : 0.2f * v; acc.x = fmaf(v, v, acc.x);
            v = fmaf(w, nz.y, xv.y); v = (v >= 0.f) ? v : 0.2f * v; acc.y = fmaf(v, v, acc.y);
            v = fmaf(w, nz.z, xv.z); v = (v >= 0.f) ? v : 0.2f * v; acc.z = fmaf(v, v, acc.z);
            v = fmaf(w, nz.w, xv.w); v = (v >= 0.f) ? v : 0.2f * v; acc.w = fmaf(v, v, acc.w);
        }
        *(float4*)(g_part + ((size_t)cc * B_ + b) * HW_ + px) = acc;
    } else {
        // ----- style GEMM -----
        __shared__ float ss[S_];
        __shared__ float sp[256];
        const int gb = blockIdx.x - K1_BLOCKS;   // 0..255
        const int b = gb >> 4, chunk = gb & 15;  // 16 chunks of 64 cols
        for (int i = tid; i < S_; i += 256) ss[i] = style[b * S_ + i];
        __syncthreads();

        const int col = chunk * 64 + (tid & 63);
        const int k0  = (tid >> 6) * 128;        // 4 K-slices of 128
        float acc = 0.f;
#pragma unroll 8
        for (int k = k0; k < k0 + 128; k++)
            acc = fmaf(ss[k], __ldg(W + (size_t)k * 1024 + col), acc);
        sp[tid] = acc;
        __syncthreads();
        if (tid < 64)
            g_style[b * 1024 + col] = sp[tid] + sp[tid + 64] + sp[tid + 128]
                                    + sp[tid + 192] + __ldg(bias + col);
    }
}

// ---------------------------------------------------------------------------
// K2: combine 16 partials -> invrms. 64 blocks, 256 thr x 4 px (float4).
// ---------------------------------------------------------------------------
__global__ __launch_bounds__(256) void k2_combine()
{
    const int b = blockIdx.x >> 2, tile = blockIdx.x & 3;
    const int px = tile * 1024 + threadIdx.x * 4;
    float4 s = make_float4(0.f, 0.f, 0.f, 0.f);
#pragma unroll
    for (int cc = 0; cc < NCC; cc++) {
        const float4 p = *(const float4*)(g_part + ((size_t)cc * B_ + b) * HW_ + px);
        s.x += p.x; s.y += p.y; s.z += p.z; s.w += p.w;
    }
    float4 r;
    r.x = rsqrtf(s.x * (1.f / (float)C_) + 1e-8f);
    r.y = rsqrtf(s.y * (1.f / (float)C_) + 1e-8f);
    r.z = rsqrtf(s.z * (1.f / (float)C_) + 1e-8f);
    r.w = rsqrtf(s.w * (1.f / (float)C_) + 1e-8f);
    *(float4*)(g_invrms + b * HW_ + px) = r;
}

// ---------------------------------------------------------------------------
// K3: one (b,c) plane per block (8192 blocks, 256 thr x 16 px).
//   y = leaky(x + nw[c]*noise) * invrms (regs), block-reduce mean/var,
//   out = y*(istd*scale) + (shift - mean*istd*scale)
// x via __ldcs (evict-first), out via __stcs; noise/invrms stay L2-hot.
// ---------------------------------------------------------------------------
__global__ __launch_bounds__(256) void k3_bc(
    const float* __restrict__ x,
    const float* __restrict__ noise,
    const float* __restrict__ nw,
    float* __restrict__ out)
{
    const int b = blockIdx.x >> 9;
    const int c = blockIdx.x & (C_ - 1);
    const size_t plane = ((size_t)b * C_ + c) * HW_;

    const float4* xp = (const float4*)(x + plane);
    const float4* np = (const float4*)(noise + (size_t)b * HW_);
    const float4* ip = (const float4*)(g_invrms + b * HW_);
    const float w = __ldg(nw + c);
    const int tid = threadIdx.x;

    float4 y[4];
    float sum = 0.f, sumsq = 0.f;

#pragma unroll
    for (int j = 0; j < 4; j++) {
        const int i = tid + j * 256;
        const float4 xv = __ldcs(xp + i);
        const float4 nv = __ldg(np + i);
        const float4 iv = __ldg(ip + i);
        float4 yv;
        float v;
        v = fmaf(w, nv.x, xv.x); v = (v >= 0.f) ? v : 0.2f * v; yv.x = v * iv.x;
        v = fmaf(w, nv.y, xv.y); v = (v >= 0.f) ? v : 0.2f * v; yv.y = v * iv.y;
        v = fmaf(w, nv.z, xv.z); v = (v >= 0.f) ? v : 0.2f * v; yv.z = v * iv.z;
        v = fmaf(w, nv.w, xv.w); v = (v >= 0.f) ? v : 0.2f * v; yv.w = v * iv.w;
        y[j] = yv;
        sum   += yv.x + yv.y + yv.z + yv.w;
        sumsq += yv.x * yv.x + yv.y * yv.y + yv.z * yv.z + yv.w * yv.w;
    }

    const int lane = tid & 31, warp = tid >> 5;
#pragma unroll
    for (int off = 16; off > 0; off >>= 1) {
        sum   += __shfl_xor_sync(0xFFFFFFFFu, sum,   off);
        sumsq += __shfl_xor_sync(0xFFFFFFFFu, sumsq, off);
    }
    __shared__ float s_sum[8], s_sq[8], s_stats[2];
    if (lane == 0) { s_sum[warp] = sum; s_sq[warp] = sumsq; }
    __syncthreads();
    if (tid == 0) {
        float ts = 0.f, tq = 0.f;
#pragma unroll
        for (int k = 0; k < 8; k++) { ts += s_sum[k]; tq += s_sq[k]; }
        const float mean = ts * (1.f / (float)HW_);
        const float var  = tq * (1.f / (float)HW_) - mean * mean;
        s_stats[0] = mean;
        s_stats[1] = rsqrtf(var + 1e-5f);
    }
    __syncthreads();
    const float mean = s_stats[0];
    const float istd = s_stats[1];

    const float scale = g_style[b * 1024 + c] + 1.f;   // s[:,0] + 1
    const float shift = g_style[b * 1024 + C_ + c];    // s[:,1]
    const float a = istd * scale;
    const float d = shift - mean * a;

    float4* op = (float4*)(out + plane);
#pragma unroll
    for (int j = 0; j < 4; j++) {
        const int i = tid + j * 256;
        const float4 yv = y[j];
        float4 ov;
        ov.x = fmaf(yv.x, a, d);
        ov.y = fmaf(yv.y, a, d);
        ov.z = fmaf(yv.z, a, d);
        ov.w = fmaf(yv.w, a, d);
        __stcs(op + i, ov);
    }
}

// ---------------------------------------------------------------------------
// Inputs (metadata order): x, noise, style, noise_weight, lin_W, lin_b
// Output: float32 [B, C, H, W]
// ---------------------------------------------------------------------------
extern "C" void kernel_launch(void* const* d_in, const int* in_sizes, int n_in,
                              void* d_out, int out_size)
{
    const float* x     = (const float*)d_in[0];
    const float* noise = (const float*)d_in[1];
    const float* style = (const float*)d_in[2];
    const float* nw    = (const float*)d_in[3];
    const float* lin_W = (const float*)d_in[4];
    const float* lin_b = (const float*)d_in[5];
    float* out = (float*)d_out;

    k1_fused<<<K1_BLOCKS + GEMM_BLOCKS, 256>>>(x, noise, nw, style, lin_W, lin_b);
    k2_combine<<<64, 256>>>();
    k3_bc<<<B_ * C_, 256>>>(x, noise, nw, out);
}